// round 3
// baseline (speedup 1.0000x reference)
#include <cuda_runtime.h>
#include <cstdint>

#define N_NODES 50000
#define N_EDGES 1600000
#define IN_CH 256
#define AD 64
#define ED 32

// ---------------- scratch (no allocations allowed) ----------------
__device__ float g_sums[N_NODES * AD];   // segment sums, 12.8 MB (L2-resident)
__device__ float g_counts[N_NODES];      // segment counts
__device__ int   g_is64;                 // 1 if edge_index is int64, 0 if int32

// ---------------- dtype detection for edge_index ----------------
// Values are in [0, 50000), so if stored as int64 every high 32-bit word is 0.
// If stored as int32, the odd words are src[1], src[3], ... (~0 with prob 1/50000 each).
__global__ void detect_kernel(const unsigned int* __restrict__ idx_words) {
    if (threadIdx.x == 0 && blockIdx.x == 0) {
        int ok = 1;
        #pragma unroll 1
        for (int i = 0; i < 64; i++) {
            if (idx_words[2 * i + 1] != 0u) { ok = 0; break; }
        }
        g_is64 = ok;
    }
}

// ---------------- zero the scatter accumulators ----------------
__global__ void zero_kernel() {
    int i = blockIdx.x * blockDim.x + threadIdx.x;
    if (i < N_NODES * AD) g_sums[i] = 0.0f;
    if (i < N_NODES)      g_counts[i] = 0.0f;
}

// ---------------- edge kernel: time_feat + scatter-add ----------------
// One thread per edge. edge_attr row (32 f32) in registers, W_time transposed
// in smem as [k][j] so a float4 broadcast load covers 4 outputs per k.
__global__ __launch_bounds__(256) void edge_kernel(
    const float* __restrict__ edge_attr,
    const void*  __restrict__ edge_index,
    const float* __restrict__ W_time,
    const float* __restrict__ b_time)
{
    __shared__ __align__(16) float sWt[ED * AD];  // [k][j]
    __shared__ float sB[AD];
    for (int i = threadIdx.x; i < ED * AD; i += blockDim.x) {
        int k = i / AD, j = i % AD;
        sWt[i] = W_time[j * ED + k];
    }
    for (int i = threadIdx.x; i < AD; i += blockDim.x) sB[i] = b_time[i];
    __syncthreads();

    int e = blockIdx.x * blockDim.x + threadIdx.x;
    if (e >= N_EDGES) return;

    int src;
    if (g_is64) src = (int)((const long long*)edge_index)[e];
    else        src = ((const int*)edge_index)[e];

    // load edge_attr row into registers
    float a[ED];
    const float4* ea4 = reinterpret_cast<const float4*>(edge_attr + (size_t)e * ED);
    #pragma unroll
    for (int i = 0; i < ED / 4; i++) {
        float4 v = ea4[i];
        a[4 * i + 0] = v.x; a[4 * i + 1] = v.y;
        a[4 * i + 2] = v.z; a[4 * i + 3] = v.w;
    }

    float* dst = g_sums + (size_t)src * AD;
    #pragma unroll
    for (int j0 = 0; j0 < AD; j0 += 4) {
        float acc0 = sB[j0 + 0], acc1 = sB[j0 + 1];
        float acc2 = sB[j0 + 2], acc3 = sB[j0 + 3];
        #pragma unroll
        for (int k = 0; k < ED; k++) {
            float4 w = *reinterpret_cast<const float4*>(&sWt[k * AD + j0]);
            float av = a[k];
            acc0 += w.x * av; acc1 += w.y * av;
            acc2 += w.z * av; acc3 += w.w * av;
        }
        acc0 = fmaxf(acc0, 0.0f); acc1 = fmaxf(acc1, 0.0f);
        acc2 = fmaxf(acc2, 0.0f); acc3 = fmaxf(acc3, 0.0f);
        asm volatile("red.global.add.v4.f32 [%0], {%1, %2, %3, %4};"
                     :: "l"(dst + j0), "f"(acc0), "f"(acc1), "f"(acc2), "f"(acc3)
                     : "memory");
    }
    asm volatile("red.global.add.f32 [%0], %1;"
                 :: "l"(&g_counts[src]), "f"(1.0f) : "memory");
}

// ---------------- fused node kernel ----------------
// Persistent grid (148 blocks x 512 thr), warp-per-node.
// All weights transposed into smem for conflict-free lane-consecutive access.
#define NODE_THREADS 512
#define NODE_WARPS   (NODE_THREADS / 32)
// smem float offsets
#define O_SWD 0                         // [256][64]
#define O_SWF (O_SWD + IN_CH * AD)      // [128][64]
#define O_SWU (O_SWF + 2 * AD * AD)     // [64][256]
#define O_SBD (O_SWU + AD * IN_CH)
#define O_SBF (O_SBD + AD)
#define O_SBU (O_SBF + AD)
#define O_WBUF (O_SBU + IN_CH)          // per warp: x[256] comb[128] fused[64]
#define WBUF_FLOATS 448
#define SMEM_FLOATS (O_WBUF + NODE_WARPS * WBUF_FLOATS)
#define SMEM_BYTES  (SMEM_FLOATS * 4)

__global__ __launch_bounds__(NODE_THREADS, 1) void node_kernel(
    const float* __restrict__ x,
    const float* __restrict__ W_down, const float* __restrict__ b_down,
    const float* __restrict__ W_fusion, const float* __restrict__ b_fusion,
    const float* __restrict__ W_up, const float* __restrict__ b_up,
    float* __restrict__ out)
{
    extern __shared__ __align__(16) float smem[];
    float* sWd = smem + O_SWD;
    float* sWf = smem + O_SWF;
    float* sWu = smem + O_SWU;
    float* sBd = smem + O_SBD;
    float* sBf = smem + O_SBF;
    float* sBu = smem + O_SBU;

    int tid = threadIdx.x;
    // W_down [64,256] -> sWd[k*64+j]
    for (int i = tid; i < AD * IN_CH; i += NODE_THREADS) {
        int j = i / IN_CH, k = i % IN_CH;
        sWd[k * AD + j] = W_down[i];
    }
    // W_fusion [64,128] -> sWf[c*64+j]
    for (int i = tid; i < AD * 2 * AD; i += NODE_THREADS) {
        int j = i / (2 * AD), c = i % (2 * AD);
        sWf[c * AD + j] = W_fusion[i];
    }
    // W_up [256,64] -> sWu[f*256+o]
    for (int i = tid; i < IN_CH * AD; i += NODE_THREADS) {
        int o = i / AD, f = i % AD;
        sWu[f * IN_CH + o] = W_up[i];
    }
    for (int i = tid; i < AD; i += NODE_THREADS) { sBd[i] = b_down[i]; sBf[i] = b_fusion[i]; }
    for (int i = tid; i < IN_CH; i += NODE_THREADS) sBu[i] = b_up[i];
    __syncthreads();

    int warp = tid >> 5;
    int lane = tid & 31;
    float* wx    = smem + O_WBUF + warp * WBUF_FLOATS;
    float* wcomb = wx + IN_CH;      // 128: [h1 | node_time]
    float* wfus  = wcomb + 2 * AD;  // 64

    int gw = blockIdx.x * NODE_WARPS + warp;
    int nw = gridDim.x * NODE_WARPS;

    for (int node = gw; node < N_NODES; node += nw) {
        // load x row into smem (float4, coalesced)
        const float4* xr = reinterpret_cast<const float4*>(x + (size_t)node * IN_CH);
        float4 v0 = xr[lane * 2], v1 = xr[lane * 2 + 1];
        reinterpret_cast<float4*>(wx)[lane * 2]     = v0;
        reinterpret_cast<float4*>(wx)[lane * 2 + 1] = v1;
        __syncwarp();

        // down projection: each lane computes h1[lane], h1[lane+32]
        float acc0 = sBd[lane], acc1 = sBd[lane + 32];
        #pragma unroll 8
        for (int k = 0; k < IN_CH; k++) {
            float xv = wx[k];
            acc0 += sWd[k * AD + lane]      * xv;
            acc1 += sWd[k * AD + lane + 32] * xv;
        }
        wcomb[lane]      = fmaxf(acc0, 0.0f);
        wcomb[lane + 32] = fmaxf(acc1, 0.0f);

        // scatter-mean result
        float cnt = fmaxf(g_counts[node], 1.0f);
        float inv = 1.0f / cnt;
        wcomb[64 + lane] = g_sums[(size_t)node * AD + lane]      * inv;
        wcomb[96 + lane] = g_sums[(size_t)node * AD + lane + 32] * inv;
        __syncwarp();

        // fusion: fused[lane], fused[lane+32]
        float f0 = sBf[lane], f1 = sBf[lane + 32];
        #pragma unroll 8
        for (int c = 0; c < 2 * AD; c++) {
            float cv = wcomb[c];
            f0 += sWf[c * AD + lane]      * cv;
            f1 += sWf[c * AD + lane + 32] * cv;
        }
        wfus[lane]      = fmaxf(f0, 0.0f);
        wfus[lane + 32] = fmaxf(f1, 0.0f);
        __syncwarp();

        // up projection + residual: 8 outputs per lane
        float* orow = out + (size_t)node * IN_CH;
        #pragma unroll
        for (int t = 0; t < 8; t++) {
            int o = t * 32 + lane;
            float acc = sBu[o] + wx[o];
            #pragma unroll 16
            for (int f = 0; f < AD; f++)
                acc += sWu[f * IN_CH + o] * wfus[f];
            orow[o] = acc;
        }
        __syncwarp();  // before next iteration overwrites wx
    }
}

// ---------------- launch ----------------
extern "C" void kernel_launch(void* const* d_in, const int* in_sizes, int n_in,
                              void* d_out, int out_size)
{
    const float* x        = (const float*)d_in[0];
    const void*  eidx     = d_in[1];
    const float* eattr    = (const float*)d_in[2];
    const float* W_down   = (const float*)d_in[3];
    const float* b_down   = (const float*)d_in[4];
    const float* W_time   = (const float*)d_in[5];
    const float* b_time   = (const float*)d_in[6];
    const float* W_fusion = (const float*)d_in[7];
    const float* b_fusion = (const float*)d_in[8];
    const float* W_up     = (const float*)d_in[9];
    const float* b_up     = (const float*)d_in[10];
    float* out = (float*)d_out;

    cudaFuncSetAttribute(node_kernel,
                         cudaFuncAttributeMaxDynamicSharedMemorySize, SMEM_BYTES);

    detect_kernel<<<1, 32>>>((const unsigned int*)eidx);
    zero_kernel<<<(N_NODES * AD + 255) / 256, 256>>>();
    edge_kernel<<<(N_EDGES + 255) / 256, 256>>>(eattr, eidx, W_time, b_time);
    node_kernel<<<148, NODE_THREADS, SMEM_BYTES>>>(
        x, W_down, b_down, W_fusion, b_fusion, W_up, b_up, out);
}